// round 14
// baseline (speedup 1.0000x reference)
#include <cuda_runtime.h>
#include <cuda_pipeline_primitives.h>
#include <math.h>

#define FULLMASK 0xffffffffu
#define B_ 4
#define A_ 16
#define NL_ 4096
#define DE_ 256
#define DH_ 64
#define H_ 8

// Scratch (__device__ globals; allocation-free rule)
__device__ float g_qW[64 * H_ * DE_];     // wq = lnkw ⊙ qW, per (ba,h)
__device__ float g_c[64 * 16];            // c1[ba][h], c2[ba][h]
__device__ float g_vals[B_ * NL_ * DH_];  // logmap0(demo_hyp)
__device__ float g_mh[B_ * H_ * A_ * DH_];

__device__ __forceinline__ float warp_sum(float v) {
    v += __shfl_xor_sync(FULLMASK, v, 16);
    v += __shfl_xor_sync(FULLMASK, v, 8);
    v += __shfl_xor_sync(FULLMASK, v, 4);
    v += __shfl_xor_sync(FULLMASK, v, 2);
    v += __shfl_xor_sync(FULLMASK, v, 1);
    return v;
}

// ============================================================================
// K1 (merged prep): blocks 0..63 -> qW/c1/c2; blocks 64..2111 -> vals + zero mh
// ============================================================================
__global__ void __launch_bounds__(256) k_prep(
    const float* __restrict__ curr, const float* __restrict__ Wq,
    const float* __restrict__ Wk, const float* __restrict__ lqw,
    const float* __restrict__ lqb, const float* __restrict__ lkw,
    const float* __restrict__ lkb, const float* __restrict__ hyp)
{
    const int tid = threadIdx.x;
    const int warp = tid >> 5, lane = tid & 31;
    if (blockIdx.x >= 64) {
        // logmap0(demo_hyp): warp per 64-elem row; also zero g_mh
        const int bi = blockIdx.x - 64;
        const int gw = bi * 8 + warp;    // 0..16383 rows
        const float2 v = ((const float2*)(hyp + (size_t)gw * DH_))[lane];
        float nn = warp_sum(v.x * v.x + v.y * v.y);
        float n = fmaxf(sqrtf(nn), 1e-15f);
        float u = fminf(n, 1.0f - 1e-5f);
        float f = atanhf(u) / n;
        float2 o; o.x = v.x * f; o.y = v.y * f;
        ((float2*)(g_vals + (size_t)gw * DH_))[lane] = o;
        const int idx = bi * 256 + tid;
        if (idx < B_ * H_ * A_ * DH_) g_mh[idx] = 0.f;
        return;
    }
    __shared__ float sred[256];
    __shared__ float sln[256];
    __shared__ float sq[256];
    __shared__ float spart[8][16];
    const int ba = blockIdx.x;
    float x = curr[ba * 256 + tid];
    sred[tid] = x; __syncthreads();
    for (int s = 128; s > 0; s >>= 1) { if (tid < s) sred[tid] += sred[tid + s]; __syncthreads(); }
    float mu = sred[0] * (1.f / 256.f); __syncthreads();
    float d = x - mu;
    sred[tid] = d * d; __syncthreads();
    for (int s = 128; s > 0; s >>= 1) { if (tid < s) sred[tid] += sred[tid + s]; __syncthreads(); }
    float var = sred[0] * (1.f / 256.f);
    sln[tid] = d * rsqrtf(var + 1e-5f) * lqw[tid] + lqb[tid];
    __syncthreads();

    float acc = 0.f;
    const float4* wr = (const float4*)(Wq + tid * 256);
    const float4* lr = (const float4*)sln;
#pragma unroll 8
    for (int i = 0; i < 64; i++) {
        float4 w = wr[i]; float4 l = lr[i];
        acc += w.x * l.x + w.y * l.y + w.z * l.z + w.w * l.w;
    }
    sq[tid] = acc; __syncthreads();

    const float scale = 0.17677669529663689f;  // 1/sqrt(32)
    const float mw = lkw[tid], mb = lkb[tid];
    float vh[8];
#pragma unroll
    for (int h = 0; h < 8; h++) {
        float v = 0.f;
#pragma unroll
        for (int dd = 0; dd < 32; dd++)
            v += sq[h * 32 + dd] * Wk[(h * 32 + dd) * 256 + tid];
        vh[h] = v * scale;
        g_qW[(ba * 8 + h) * 256 + tid] = vh[h] * mw;
    }
    // c1[h] = sum_e wq[e], c2[h] = sum_e lnkb[e]*qw[e] — warp partials + 1 combine
#pragma unroll
    for (int h = 0; h < 8; h++) {
        float r1 = warp_sum(vh[h] * mw);
        float r2 = warp_sum(vh[h] * mb);
        if (lane == 0) { spart[warp][h] = r1; spart[warp][h + 8] = r2; }
    }
    __syncthreads();
    if (tid < 16) {
        float s = 0.f;
#pragma unroll
        for (int w = 0; w < 8; w++) s += spart[w][tid];
        g_c[ba * 16 + tid] = s;
    }
}

// ============================================================================
// K2: scores — HEAD-SPLIT redesign. k_scores is FFMA-rt-bound (~40us floor,
// 79 fma-instr/row x rt2); the old 64-reg qW file capped us at 4 warps/SMSP
// and overlap losses cost ~32us. Now: block owns ONE 32-row chunk; warp
// pairs split heads (4 each -> qW = 32 regs -> fits (256,3) 85-reg cap ->
// 6 warps/SMSP). Rows staged block-cooperatively (cp.async, 2 halves,
// double-buffered); even warps write mu/inv to smem once per row; both
// warps do 4-head dots + shallow depth-5 butterfly.
// Grid: 8192 blocks (64 ba x 128 chunks).
// ============================================================================
#define MERGE(out, lo, hi, pd, dd) { \
    float _sel = (pd) ? (hi) : (lo); \
    float _oth = (pd) ? (lo) : (hi); \
    out = _sel + __shfl_xor_sync(FULLMASK, _oth, dd); }

__global__ void __launch_bounds__(256, 3) k_scores(
    const float* __restrict__ rho, const int* __restrict__ mask,
    float* __restrict__ attn)
{
    __shared__ float srows[32 * 256];   // 32 KB: this block's 32 rho rows
    __shared__ float stile[8 * 33];     // scores staging [h][row]
    __shared__ float smu[32], sinv[32];
    const int tid = threadIdx.x;
    const int warp = tid >> 5, lane = tid & 31;
    const int ba = blockIdx.x >> 7;          // 128 chunks per ba
    const int chunk = blockIdx.x & 127;
    const int b = ba >> 4, a = ba & 15;
    const int x0 = chunk << 5;

    // head group: warps 0,2,4,6 -> heads 0..3 (+ sums duty); 1,3,5,7 -> 4..7
    const int hg = (warp & 1) * 4;
    const int rsub = warp >> 1;              // row subset: rows rsub + 4i

    // qW for my 4 heads, my k-slice (32 regs)
    float4 qw0[4], qw1[4];
#pragma unroll
    for (int h = 0; h < 4; h++) {
        const float4* p = (const float4*)(g_qW + (ba * 8 + hg + h) * 256);
        qw0[h] = p[lane]; qw1[h] = p[32 + lane];
    }
    const float myc1 = g_c[ba * 16 + hg + (lane & 3)];
    const float myc2 = g_c[ba * 16 + 8 + hg + (lane & 3)];
    const bool pb1 = lane & 1, pb2 = lane & 2;

    // cooperative cp.async: 8 float4 per thread; first 4 = rows 0..15
    const float4* rho4 = (const float4*)(rho + ((size_t)(b * NL_ + x0) * 16 + a) * 256);
#pragma unroll
    for (int c = 0; c < 4; c++) {
        const int f = tid + c * 256;         // float4 idx < 1024 (rows 0..15)
        __pipeline_memcpy_async(&srows[f * 4], &rho4[(size_t)(f >> 6) * 1024 + (f & 63)], 16);
    }
    __pipeline_commit();
#pragma unroll
    for (int c = 4; c < 8; c++) {
        const int f = tid + c * 256;         // rows 16..31
        __pipeline_memcpy_async(&srows[f * 4], &rho4[(size_t)(f >> 6) * 1024 + (f & 63)], 16);
    }
    __pipeline_commit();

#pragma unroll
    for (int half = 0; half < 2; half++) {
        __pipeline_wait_prior(1 - half);
        __syncthreads();                     // staged data visible block-wide
        const int r0 = half * 16;

        // even warps: sums for their 4 rows of this half -> smu/sinv
        if ((warp & 1) == 0) {
#pragma unroll
            for (int i = 0; i < 4; i++) {
                const int r = r0 + rsub + 4 * i;
                const float4* rp = (const float4*)&srows[r * 256];
                const float4 d0 = rp[lane], d1 = rp[32 + lane];
                float sum = ((d0.x + d0.y) + (d0.z + d0.w)) + ((d1.x + d1.y) + (d1.z + d1.w));
                float ssq = d0.x * d0.x;
                ssq = fmaf(d0.y, d0.y, ssq); ssq = fmaf(d0.z, d0.z, ssq); ssq = fmaf(d0.w, d0.w, ssq);
                ssq = fmaf(d1.x, d1.x, ssq); ssq = fmaf(d1.y, d1.y, ssq);
                ssq = fmaf(d1.z, d1.z, ssq); ssq = fmaf(d1.w, d1.w, ssq);
                float t; MERGE(t, sum, ssq, pb1, 1);
                t += __shfl_xor_sync(FULLMASK, t, 2);
                t += __shfl_xor_sync(FULLMASK, t, 4);
                t += __shfl_xor_sync(FULLMASK, t, 8);
                t += __shfl_xor_sync(FULLMASK, t, 16);
                const float sT = __shfl_sync(FULLMASK, t, 0);
                const float qT = __shfl_sync(FULLMASK, t, 1);
                const float mu = sT * (1.f / 256.f);
                const float inv = rsqrtf(fmaf(-mu, mu, qT * (1.f / 256.f)) + 1e-5f);
                if (lane == 0) { smu[r] = mu; sinv[r] = inv; }
            }
        }
        __syncthreads();                     // smu/sinv ready

        // all warps: 4-head dots + shallow butterfly + fold for their 4 rows
#pragma unroll
        for (int i = 0; i < 4; i++) {
            const int r = r0 + rsub + 4 * i;
            const float4* rp = (const float4*)&srows[r * 256];
            const float4 d0 = rp[lane], d1 = rp[32 + lane];
            float acc[4];
#pragma unroll
            for (int h = 0; h < 4; h++) {
                float t = d0.x * qw0[h].x;
                t = fmaf(d0.y, qw0[h].y, t); t = fmaf(d0.z, qw0[h].z, t); t = fmaf(d0.w, qw0[h].w, t);
                t = fmaf(d1.x, qw1[h].x, t); t = fmaf(d1.y, qw1[h].y, t);
                t = fmaf(d1.z, qw1[h].z, t); t = fmaf(d1.w, qw1[h].w, t);
                acc[h] = t;
            }
            float m0, m1, p;
            MERGE(m0, acc[0], acc[1], pb1, 1);
            MERGE(m1, acc[2], acc[3], pb1, 1);
            MERGE(p, m0, m1, pb2, 2);        // lane&3 -> head offset
            p += __shfl_xor_sync(FULLMASK, p, 4);
            p += __shfl_xor_sync(FULLMASK, p, 8);
            p += __shfl_xor_sync(FULLMASK, p, 16);
            const float mu = smu[r], inv = sinv[r];
            const float sc = fmaf(inv, fmaf(-mu, myc1, p), myc2);
            if (lane < 4) stile[(hg + lane) * 33 + r] = sc;
        }
    }
    __syncthreads();
    // coalesced store: warp w handles head w for this chunk
    const int mymask = mask[b * NL_ + x0 + lane];
    const float v = stile[warp * 33 + lane];
    attn[((size_t)((b * 8 + warp) * 16 + a)) * NL_ + x0 + lane] = mymask ? v : -INFINITY;
}

// ============================================================================
// K3: softmax, register-resident float4 per thread, 1024 threads/block
// ============================================================================
__global__ void __launch_bounds__(1024) k_softmax(float* __restrict__ attn)
{
    __shared__ float sred[32];
    const int tid = threadIdx.x, lane = tid & 31, wid = tid >> 5;
    float4* p = (float4*)(attn + (size_t)blockIdx.x * NL_);
    float4 v = p[tid];
    float mx = fmaxf(fmaxf(v.x, v.y), fmaxf(v.z, v.w));
    for (int d = 16; d; d >>= 1) mx = fmaxf(mx, __shfl_xor_sync(FULLMASK, mx, d));
    if (lane == 0) sred[wid] = mx;
    __syncthreads();
    if (wid == 0) {
        float m = sred[lane];
        for (int d = 16; d; d >>= 1) m = fmaxf(m, __shfl_xor_sync(FULLMASK, m, d));
        if (lane == 0) sred[0] = m;
    }
    __syncthreads();
    mx = sred[0];
    __syncthreads();
    v.x = __expf(v.x - mx); v.y = __expf(v.y - mx);
    v.z = __expf(v.z - mx); v.w = __expf(v.w - mx);
    float s = (v.x + v.y) + (v.z + v.w);
    for (int d = 16; d; d >>= 1) s += __shfl_xor_sync(FULLMASK, s, d);
    if (lane == 0) sred[wid] = s;
    __syncthreads();
    if (wid == 0) {
        float m = sred[lane];
        for (int d = 16; d; d >>= 1) m += __shfl_xor_sync(FULLMASK, m, d);
        if (lane == 0) sred[0] = m;
    }
    __syncthreads();
    const float inv = 1.0f / sred[0];
    v.x *= inv; v.y *= inv; v.z *= inv; v.w *= inv;
    p[tid] = v;
}

// ============================================================================
// K5: m_h = attn @ vals. Same warp-level work as R10 best (8 a-rows/warp,
// 1 LDG.64 + 8 SHFL + 16 FFMA per j) repacked into 128-thread blocks,
// grid (B,H,64) = 2048 blocks -> ~10 blocks/SM, occupancy 48 -> ~65%.
// ============================================================================
__global__ void __launch_bounds__(128) k_mh(const float* __restrict__ attn)
{
    const int b = blockIdx.x, h = blockIdx.y, xs = blockIdx.z;  // xs 0..63
    const int warp = threadIdx.x >> 5, lane = threadIdx.x & 31;
    const int sub = warp & 1;            // 32-x chunk within the 64-x slice
    const int a0 = (warp >> 1) * 8;      // 8 a-rows per warp
    const int x0 = xs * 64 + sub * 32;

    const float* arow = attn + ((size_t)((b * 8 + h) * 16 + a0)) * NL_ + x0;
    float att[8];
#pragma unroll
    for (int i = 0; i < 8; i++) att[i] = arow[(size_t)i * NL_ + lane];

    const float2* vp = (const float2*)(g_vals + ((size_t)(b * NL_) + x0) * 64) + lane;
    float2 acc[8] = {};
#pragma unroll 8
    for (int j = 0; j < 32; j++) {
        const float2 v = vp[j * 32];
#pragma unroll
        for (int i = 0; i < 8; i++) {
            const float av = __shfl_sync(FULLMASK, att[i], j);
            acc[i].x = fmaf(av, v.x, acc[i].x);
            acc[i].y = fmaf(av, v.y, acc[i].y);
        }
    }
    float* m0 = g_mh + ((size_t)(b * 8 + h) * 16 + a0) * 64 + 2 * lane;
#pragma unroll
    for (int i = 0; i < 8; i++) {
        atomicAdd(m0 + i * 64,     acc[i].x);
        atomicAdd(m0 + i * 64 + 1, acc[i].y);
    }
}

// ============================================================================
// K6: tail — log/exp maps, means, radius clamp
// ============================================================================
__global__ void __launch_bounds__(256) k_tail(float* __restrict__ out)
{
    __shared__ float shyp[16][DH_];
    const int b = blockIdx.x;
    const int warp = threadIdx.x >> 5, lane = threadIdx.x & 31;

    for (int ai = 0; ai < 2; ai++) {
        const int a = warp + ai * 8;
        float t0 = 0.f, t1 = 0.f;
        for (int h = 0; h < H_; h++) {
            const float2 m = ((const float2*)(g_mh + ((size_t)(b * H_ + h) * 16 + a) * DH_))[lane];
            float nn = warp_sum(m.x * m.x + m.y * m.y);
            float n = fmaxf(sqrtf(nn), 1e-15f);
            float ce = tanhf(n) / n;
            float ex = m.x * ce, ey = m.y * ce;
            float nn2 = warp_sum(ex * ex + ey * ey);
            float n2 = fmaxf(sqrtf(nn2), 1e-15f);
            float u = fminf(n2, 1.0f - 1e-5f);
            float f = atanhf(u) / n2;
            t0 += ex * f; t1 += ey * f;
        }
        t0 *= (1.0f / H_); t1 *= (1.0f / H_);
        float nn = warp_sum(t0 * t0 + t1 * t1);
        float n = fmaxf(sqrtf(nn), 1e-15f);
        float ce = tanhf(n) / n;
        float cx = t0 * ce, cy = t1 * ce;
        float nn2 = warp_sum(cx * cx + cy * cy);
        float nc = fmaxf(sqrtf(nn2), 1e-6f);
        float sc = fminf((1.0f - 1e-5f) / nc, 1.0f);
        shyp[a][lane * 2] = cx * sc;
        shyp[a][lane * 2 + 1] = cy * sc;
    }
    __syncthreads();
    if (threadIdx.x < DH_) {
        float s = 0.f;
        for (int a = 0; a < 16; a++) s += shyp[a][threadIdx.x];
        out[b * DH_ + threadIdx.x] = s * (1.0f / 16.0f);
    }
}

// ============================================================================
extern "C" void kernel_launch(void* const* d_in, const int* in_sizes, int n_in,
                              void* d_out, int out_size)
{
    const float* curr = (const float*)d_in[0];
    const float* rho  = (const float*)d_in[1];
    const float* hyp  = (const float*)d_in[2];
    const int*   mask = (const int*)d_in[3];
    const float* Wq   = (const float*)d_in[4];
    const float* Wk   = (const float*)d_in[5];
    const float* lqw  = (const float*)d_in[6];
    const float* lqb  = (const float*)d_in[7];
    const float* lkw  = (const float*)d_in[8];
    const float* lkb  = (const float*)d_in[9];

    float* out  = (float*)d_out;
    float* attn = out + B_ * DH_;

    k_prep<<<2112, 256>>>(curr, Wq, Wk, lqw, lqb, lkw, lkb, hyp);
    k_scores<<<8192, 256>>>(rho, mask, attn);
    k_softmax<<<512, 1024>>>(attn);
    dim3 g5(B_, H_, 64);
    k_mh<<<g5, 128>>>(attn);
    k_tail<<<B_, 256>>>(out);
}

// round 15
// speedup vs baseline: 1.4540x; 1.4540x over previous
#include <cuda_runtime.h>
#include <cuda_pipeline_primitives.h>
#include <math.h>

#define FULLMASK 0xffffffffu
#define B_ 4
#define A_ 16
#define NL_ 4096
#define DE_ 256
#define DH_ 64
#define H_ 8
#define STAGES 6

// Scratch (__device__ globals; allocation-free rule)
__device__ float g_qW[64 * H_ * DE_];     // wq = lnkw ⊙ qW, per (ba,h)
__device__ float g_c[64 * 16];            // c1[ba][h], c2[ba][h]
__device__ float g_vals[B_ * NL_ * DH_];  // logmap0(demo_hyp)
__device__ float g_mh[B_ * H_ * A_ * DH_];

__device__ __forceinline__ float warp_sum(float v) {
    v += __shfl_xor_sync(FULLMASK, v, 16);
    v += __shfl_xor_sync(FULLMASK, v, 8);
    v += __shfl_xor_sync(FULLMASK, v, 4);
    v += __shfl_xor_sync(FULLMASK, v, 2);
    v += __shfl_xor_sync(FULLMASK, v, 1);
    return v;
}

// ============================================================================
// K1a: qW/c1/c2 — grid 512 = (ba,h). 8x more parallelism than the old 64-block
// version (which left half the GPU idle). Warp-coalesced GEMV for the
// 32-element q-slice this head needs; warp-partial LN reductions.
// ============================================================================
__global__ void __launch_bounds__(256) k_prep_qw(
    const float* __restrict__ curr, const float* __restrict__ Wq,
    const float* __restrict__ Wk, const float* __restrict__ lqw,
    const float* __restrict__ lqb, const float* __restrict__ lkw,
    const float* __restrict__ lkb)
{
    __shared__ float sp[16];
    __shared__ float sln[256];
    __shared__ float sq[32];
    const int tid = threadIdx.x;
    const int warp = tid >> 5, lane = tid & 31;
    const int ba = blockIdx.x >> 3, h = blockIdx.x & 7;

    // LN of curr[ba] via warp partials
    const float x = curr[ba * 256 + tid];
    float ws = warp_sum(x);
    if (lane == 0) sp[warp] = ws;
    __syncthreads();
    float tot = 0.f;
#pragma unroll
    for (int w = 0; w < 8; w++) tot += sp[w];
    const float mu = tot * (1.f / 256.f);
    const float d = x - mu;
    float ws2 = warp_sum(d * d);
    if (lane == 0) sp[8 + warp] = ws2;
    __syncthreads();
    float vtot = 0.f;
#pragma unroll
    for (int w = 0; w < 8; w++) vtot += sp[8 + w];
    const float var = vtot * (1.f / 256.f);
    sln[tid] = d * rsqrtf(var + 1e-5f) * lqw[tid] + lqb[tid];
    __syncthreads();

    // q-slice this head needs: q[h*32+dd] = sum_e sln[e] * Wq[(h*32+dd)*256+e]
    // warp w computes dd = w*4..w*4+3; lane owns 8 consecutive e (coalesced)
#pragma unroll
    for (int i = 0; i < 4; i++) {
        const int dd = warp * 4 + i;
        const float4* wrow = (const float4*)(Wq + (size_t)(h * 32 + dd) * 256);
        const float4 w0 = wrow[2 * lane], w1 = wrow[2 * lane + 1];
        const float4 l0 = ((const float4*)sln)[2 * lane];
        const float4 l1 = ((const float4*)sln)[2 * lane + 1];
        float t = w0.x * l0.x;
        t = fmaf(w0.y, l0.y, t); t = fmaf(w0.z, l0.z, t); t = fmaf(w0.w, l0.w, t);
        t = fmaf(w1.x, l1.x, t); t = fmaf(w1.y, l1.y, t);
        t = fmaf(w1.z, l1.z, t); t = fmaf(w1.w, l1.w, t);
        t = warp_sum(t);
        if (lane == 0) sq[dd] = t;
    }
    __syncthreads();

    // qW[ba,h][tid] = scale * sum_dd sq[dd] * Wk[(h*32+dd)*256 + tid]
    const float mwv = lkw[tid], mbv = lkb[tid];
    float v = 0.f;
#pragma unroll
    for (int dd = 0; dd < 32; dd++)
        v = fmaf(sq[dd], Wk[(size_t)(h * 32 + dd) * 256 + tid], v);
    v *= 0.17677669529663689f;               // 1/sqrt(32)
    g_qW[(ba * 8 + h) * 256 + tid] = v * mwv;

    // c1 = sum_e qW, c2 = sum_e v*lkb
    float r1 = warp_sum(v * mwv);
    float r2 = warp_sum(v * mbv);
    if (lane == 0) { sp[warp] = r1; sp[8 + warp] = r2; }
    __syncthreads();
    if (tid == 0) {
        float s = 0.f;
#pragma unroll
        for (int w = 0; w < 8; w++) s += sp[w];
        g_c[ba * 16 + h] = s;
    }
    if (tid == 1) {
        float s = 0.f;
#pragma unroll
        for (int w = 0; w < 8; w++) s += sp[8 + w];
        g_c[ba * 16 + 8 + h] = s;
    }
}

// ============================================================================
// K1b: vals = logmap0(demo_hyp) + zero g_mh. Runs on a forked stream,
// concurrent with k_scores (no dependency), joins before k_mh.
// ============================================================================
__global__ void __launch_bounds__(256) k_prep_vals(const float* __restrict__ hyp)
{
    const int tid = threadIdx.x;
    const int warp = tid >> 5, lane = tid & 31;
    const int gw = blockIdx.x * 8 + warp;    // 0..16383 rows
    const float2 v = ((const float2*)(hyp + (size_t)gw * DH_))[lane];
    float nn = warp_sum(v.x * v.x + v.y * v.y);
    float n = fmaxf(sqrtf(nn), 1e-15f);
    float u = fminf(n, 1.0f - 1e-5f);
    float f = atanhf(u) / n;
    float2 o; o.x = v.x * f; o.y = v.y * f;
    ((float2*)(g_vals + (size_t)gw * DH_))[lane] = o;
    const int idx = blockIdx.x * 256 + tid;
    if (idx < B_ * H_ * A_ * DH_) g_mh[idx] = 0.f;
}

// ============================================================================
// K2: scores — R10 version VERBATIM (proven local optimum: smem-qW/2-row-ILP/
// minBlocks3/fused-butterfly/head-split all regressed, R4..R14).
// ============================================================================
#define MERGE(out, lo, hi, pd, dd) { \
    float _sel = (pd) ? (hi) : (lo); \
    float _oth = (pd) ? (lo) : (hi); \
    out = _sel + __shfl_xor_sync(FULLMASK, _oth, dd); }

__device__ __forceinline__ void process_row(
    const float4 r0, const float4 r1, const int j,
    const int lane, const bool pb1, const bool pb2, const bool pb4,
    const float4* __restrict__ qw0, const float4* __restrict__ qw1,
    const float myc1, const float myc2, float* __restrict__ stw)
{
    float sum = ((r0.x + r0.y) + (r0.z + r0.w)) + ((r1.x + r1.y) + (r1.z + r1.w));
    float ssq = r0.x * r0.x;
    ssq = fmaf(r0.y, r0.y, ssq); ssq = fmaf(r0.z, r0.z, ssq); ssq = fmaf(r0.w, r0.w, ssq);
    ssq = fmaf(r1.x, r1.x, ssq); ssq = fmaf(r1.y, r1.y, ssq);
    ssq = fmaf(r1.z, r1.z, ssq); ssq = fmaf(r1.w, r1.w, ssq);

    float acc[8];
#pragma unroll
    for (int h = 0; h < 8; h++) {
        float t = r0.x * qw0[h].x;
        t = fmaf(r0.y, qw0[h].y, t); t = fmaf(r0.z, qw0[h].z, t); t = fmaf(r0.w, qw0[h].w, t);
        t = fmaf(r1.x, qw1[h].x, t); t = fmaf(r1.y, qw1[h].y, t);
        t = fmaf(r1.z, qw1[h].z, t); t = fmaf(r1.w, qw1[h].w, t);
        acc[h] = t;
    }
    float m0, m1, m2, m3, n0, n1, p;
    MERGE(m0, acc[0], acc[1], pb1, 1); MERGE(m1, acc[2], acc[3], pb1, 1);
    MERGE(m2, acc[4], acc[5], pb1, 1); MERGE(m3, acc[6], acc[7], pb1, 1);
    MERGE(n0, m0, m1, pb2, 2); MERGE(n1, m2, m3, pb2, 2);
    MERGE(p, n0, n1, pb4, 4);
    p += __shfl_xor_sync(FULLMASK, p, 8);
    p += __shfl_xor_sync(FULLMASK, p, 16);
    float t; MERGE(t, sum, ssq, pb1, 1);
    t += __shfl_xor_sync(FULLMASK, t, 2);
    t += __shfl_xor_sync(FULLMASK, t, 4);
    t += __shfl_xor_sync(FULLMASK, t, 8);
    t += __shfl_xor_sync(FULLMASK, t, 16);
    float o = __shfl_xor_sync(FULLMASK, t, 1);
    float sT = pb1 ? o : t;
    float qT = pb1 ? t : o;
    float mu  = sT * (1.f / 256.f);
    float inv = rsqrtf(fmaf(-mu, mu, qT * (1.f / 256.f)) + 1e-5f);
    float sc  = fmaf(inv, fmaf(-mu, myc1, p), myc2);
    if (lane < 8) stw[lane * 33 + j] = sc;
}

__global__ void __launch_bounds__(256, 2) k_scores(
    const float* __restrict__ rho, const int* __restrict__ mask,
    float* __restrict__ attn)
{
    __shared__ float srow[8][STAGES][256];   // 48 KB: 6-row pipeline per warp
    __shared__ float stile[8][8 * 33];
    const int warp = threadIdx.x >> 5, lane = threadIdx.x & 31;
    const int gw = blockIdx.x * 8 + warp;
    const int ba = gw >> 7, chunk = gw & 127;
    const int b = ba >> 4, a = ba & 15;
    const int x0 = chunk << 5;

    float4 qw0[8], qw1[8];
#pragma unroll
    for (int h = 0; h < 8; h++) {
        const float4* p = (const float4*)(g_qW + (ba * 8 + h) * 256);
        qw0[h] = p[lane]; qw1[h] = p[32 + lane];
    }
    const float myc1 = g_c[ba * 16 + (lane & 7)];
    const float myc2 = g_c[ba * 16 + 8 + (lane & 7)];
    const bool pb1 = lane & 1, pb2 = lane & 2, pb4 = lane & 4;
    float* stw = &stile[warp][0];

    const float* base = rho + ((size_t)(b * NL_ + x0) * 16 + a) * 256;

#pragma unroll
    for (int s = 0; s < STAGES; s++) {
        const float4* src = (const float4*)(base + (size_t)s * 4096);
        __pipeline_memcpy_async(&srow[warp][s][lane * 4],       &src[lane],      16);
        __pipeline_memcpy_async(&srow[warp][s][128 + lane * 4], &src[32 + lane], 16);
        __pipeline_commit();
    }

    int st = 0;
#pragma unroll 1
    for (int j = 0; j < 32; j++) {
        __pipeline_wait_prior(STAGES - 1);
        const float4 r0 = *(const float4*)&srow[warp][st][lane * 4];
        const float4 r1 = *(const float4*)&srow[warp][st][128 + lane * 4];
        if (j + STAGES < 32) {
            const float4* src = (const float4*)(base + (size_t)(j + STAGES) * 4096);
            __pipeline_memcpy_async(&srow[warp][st][lane * 4],       &src[lane],      16);
            __pipeline_memcpy_async(&srow[warp][st][128 + lane * 4], &src[32 + lane], 16);
        }
        __pipeline_commit();
        process_row(r0, r1, j, lane, pb1, pb2, pb4, qw0, qw1, myc1, myc2, stw);
        if (++st == STAGES) st = 0;
    }
    __syncwarp();
    const int mymask = mask[b * NL_ + x0 + lane];
#pragma unroll
    for (int h = 0; h < 8; h++) {
        float v = stw[h * 33 + lane];
        attn[((size_t)((b * 8 + h) * 16 + a)) * NL_ + x0 + lane] = mymask ? v : -INFINITY;
    }
}

// ============================================================================
// K3: softmax, register-resident float4 per thread, 1024 threads/block
// ============================================================================
__global__ void __launch_bounds__(1024) k_softmax(float* __restrict__ attn)
{
    __shared__ float sred[32];
    const int tid = threadIdx.x, lane = tid & 31, wid = tid >> 5;
    float4* p = (float4*)(attn + (size_t)blockIdx.x * NL_);
    float4 v = p[tid];
    float mx = fmaxf(fmaxf(v.x, v.y), fmaxf(v.z, v.w));
    for (int d = 16; d; d >>= 1) mx = fmaxf(mx, __shfl_xor_sync(FULLMASK, mx, d));
    if (lane == 0) sred[wid] = mx;
    __syncthreads();
    if (wid == 0) {
        float m = sred[lane];
        for (int d = 16; d; d >>= 1) m = fmaxf(m, __shfl_xor_sync(FULLMASK, m, d));
        if (lane == 0) sred[0] = m;
    }
    __syncthreads();
    mx = sred[0];
    __syncthreads();
    v.x = __expf(v.x - mx); v.y = __expf(v.y - mx);
    v.z = __expf(v.z - mx); v.w = __expf(v.w - mx);
    float s = (v.x + v.y) + (v.z + v.w);
    for (int d = 16; d; d >>= 1) s += __shfl_xor_sync(FULLMASK, s, d);
    if (lane == 0) sred[wid] = s;
    __syncthreads();
    if (wid == 0) {
        float m = sred[lane];
        for (int d = 16; d; d >>= 1) m += __shfl_xor_sync(FULLMASK, m, d);
        if (lane == 0) sred[0] = m;
    }
    __syncthreads();
    const float inv = 1.0f / sred[0];
    v.x *= inv; v.y *= inv; v.z *= inv; v.w *= inv;
    p[tid] = v;
}

// ============================================================================
// K5: m_h = attn @ vals — R10 version verbatim (8 a-rows/warp, grid (B,H,32)).
// ============================================================================
__global__ void __launch_bounds__(256) k_mh(const float* __restrict__ attn)
{
    const int b = blockIdx.x, h = blockIdx.y, xs = blockIdx.z;  // xs 0..31
    const int warp = threadIdx.x >> 5, lane = threadIdx.x & 31;
    const int sub = warp & 3;
    const int a0 = (warp >> 2) * 8;
    const int x0 = xs * 128 + sub * 32;

    const float* arow = attn + ((size_t)((b * 8 + h) * 16 + a0)) * NL_ + x0;
    float att[8];
#pragma unroll
    for (int i = 0; i < 8; i++) att[i] = arow[(size_t)i * NL_ + lane];

    const float2* vp = (const float2*)(g_vals + ((size_t)(b * NL_) + x0) * 64) + lane;
    float2 acc[8] = {};
#pragma unroll 8
    for (int j = 0; j < 32; j++) {
        const float2 v = vp[j * 32];
#pragma unroll
        for (int i = 0; i < 8; i++) {
            const float av = __shfl_sync(FULLMASK, att[i], j);
            acc[i].x = fmaf(av, v.x, acc[i].x);
            acc[i].y = fmaf(av, v.y, acc[i].y);
        }
    }
    float* m0 = g_mh + ((size_t)(b * 8 + h) * 16 + a0) * 64 + 2 * lane;
#pragma unroll
    for (int i = 0; i < 8; i++) {
        atomicAdd(m0 + i * 64,     acc[i].x);
        atomicAdd(m0 + i * 64 + 1, acc[i].y);
    }
}

// ============================================================================
// K6: tail — log/exp maps, means, radius clamp
// ============================================================================
__global__ void __launch_bounds__(256) k_tail(float* __restrict__ out)
{
    __shared__ float shyp[16][DH_];
    const int b = blockIdx.x;
    const int warp = threadIdx.x >> 5, lane = threadIdx.x & 31;

    for (int ai = 0; ai < 2; ai++) {
        const int a = warp + ai * 8;
        float t0 = 0.f, t1 = 0.f;
        for (int h = 0; h < H_; h++) {
            const float2 m = ((const float2*)(g_mh + ((size_t)(b * H_ + h) * 16 + a) * DH_))[lane];
            float nn = warp_sum(m.x * m.x + m.y * m.y);
            float n = fmaxf(sqrtf(nn), 1e-15f);
            float ce = tanhf(n) / n;
            float ex = m.x * ce, ey = m.y * ce;
            float nn2 = warp_sum(ex * ex + ey * ey);
            float n2 = fmaxf(sqrtf(nn2), 1e-15f);
            float u = fminf(n2, 1.0f - 1e-5f);
            float f = atanhf(u) / n2;
            t0 += ex * f; t1 += ey * f;
        }
        t0 *= (1.0f / H_); t1 *= (1.0f / H_);
        float nn = warp_sum(t0 * t0 + t1 * t1);
        float n = fmaxf(sqrtf(nn), 1e-15f);
        float ce = tanhf(n) / n;
        float cx = t0 * ce, cy = t1 * ce;
        float nn2 = warp_sum(cx * cx + cy * cy);
        float nc = fmaxf(sqrtf(nn2), 1e-6f);
        float sc = fminf((1.0f - 1e-5f) / nc, 1.0f);
        shyp[a][lane * 2] = cx * sc;
        shyp[a][lane * 2 + 1] = cy * sc;
    }
    __syncthreads();
    if (threadIdx.x < DH_) {
        float s = 0.f;
        for (int a = 0; a < 16; a++) s += shyp[a][threadIdx.x];
        out[b * DH_ + threadIdx.x] = s * (1.0f / 16.0f);
    }
}

// ============================================================================
// Launch: stream-fork so k_prep_vals runs concurrently with k_prep_qw +
// k_scores; join before k_mh. Stream/events created once on the first
// (uncaptured correctness) call; the record/wait ops are captured per call.
// ============================================================================
extern "C" void kernel_launch(void* const* d_in, const int* in_sizes, int n_in,
                              void* d_out, int out_size)
{
    const float* curr = (const float*)d_in[0];
    const float* rho  = (const float*)d_in[1];
    const float* hyp  = (const float*)d_in[2];
    const int*   mask = (const int*)d_in[3];
    const float* Wq   = (const float*)d_in[4];
    const float* Wk   = (const float*)d_in[5];
    const float* lqw  = (const float*)d_in[6];
    const float* lqb  = (const float*)d_in[7];
    const float* lkw  = (const float*)d_in[8];
    const float* lkb  = (const float*)d_in[9];

    float* out  = (float*)d_out;
    float* attn = out + B_ * DH_;

    static cudaStream_t s2 = nullptr;
    static cudaEvent_t evFork = nullptr, evJoin = nullptr;
    if (s2 == nullptr) {
        cudaStreamCreateWithFlags(&s2, cudaStreamNonBlocking);
        cudaEventCreateWithFlags(&evFork, cudaEventDisableTiming);
        cudaEventCreateWithFlags(&evJoin, cudaEventDisableTiming);
    }

    // fork: vals + mh-zero on side stream
    cudaEventRecord(evFork, 0);
    cudaStreamWaitEvent(s2, evFork, 0);
    k_prep_vals<<<2048, 256, 0, s2>>>(hyp);
    cudaEventRecord(evJoin, s2);

    // main: qW -> scores -> softmax
    k_prep_qw<<<512, 256>>>(curr, Wq, Wk, lqw, lqb, lkw, lkb);
    k_scores<<<1024, 256>>>(rho, mask, attn);
    k_softmax<<<512, 1024>>>(attn);

    // join: mh needs vals + zeroed g_mh
    cudaStreamWaitEvent(0, evJoin, 0);
    dim3 g5(B_, H_, 32);
    k_mh<<<g5, 256>>>(attn);
    k_tail<<<B_, 256>>>(out);
}